// round 6
// baseline (speedup 1.0000x reference)
#include <cuda_runtime.h>
#include <cuda_bf16.h>
#include <math.h>
#include <stdint.h>

#define NROWS 4096
#define DIM   1024
#define EPS   1e-8f

// GEMM tiling
#define BM 128
#define BN 128
#define BK 64                      // bf16 K per smem tile (128 B rows -> SW128 swizzle)
#define NTILES_K (DIM / BK)        // 16
#define NPARTS 3                   // hi*hi, hi*lo, lo*hi
#define NTILES (NPARTS * NTILES_K) // 48

// dynamic smem: 3 stages x (A 16KB + B 16KB)
#define SMEM_STAGE  32768
#define SMEM_BOFF   16384
#define NSTAGES 3
#define SMEM_TOTAL  (NSTAGES * SMEM_STAGE)   // 98304

// Scratch (no device allocation allowed -> __device__ globals)
__device__ __nv_bfloat16 g_Ahi[NROWS * DIM];
__device__ __nv_bfloat16 g_Alo[NROWS * DIM];
__device__ __nv_bfloat16 g_Bhi[NROWS * DIM];
__device__ __nv_bfloat16 g_Blo[NROWS * DIM];
__device__ float g_tn[NROWS];
__device__ float g_sn[NROWS];

// ---------------------------------------------------------------------------
// helpers
// ---------------------------------------------------------------------------
__device__ __forceinline__ uint32_t smem_u32(const void* p) {
    uint32_t a;
    asm("{ .reg .u64 t; cvta.to.shared.u64 t, %1; cvt.u32.u64 %0, t; }"
        : "=r"(a) : "l"(p));
    return a;
}
__device__ __forceinline__ void cp16(uint32_t dst, const void* src) {
    asm volatile("cp.async.cg.shared.global [%0], [%1], 16;"
                 :: "r"(dst), "l"(src));
}
#define CP_COMMIT() asm volatile("cp.async.commit_group;" ::: "memory")
#define CP_WAIT(n)  asm volatile("cp.async.wait_group %0;" :: "n"(n) : "memory")

__device__ __forceinline__ uint32_t swz(uint32_t o) {   // SW128: bits[6:4] ^= bits[9:7]
    return o ^ ((o >> 3) & 0x70);
}
__device__ __forceinline__ void ldsm4(uint32_t* r, uint32_t a) {
    asm volatile("ldmatrix.sync.aligned.m8n8.x4.shared.b16 {%0,%1,%2,%3}, [%4];"
                 : "=r"(r[0]), "=r"(r[1]), "=r"(r[2]), "=r"(r[3]) : "r"(a));
}
__device__ __forceinline__ void mma16816(float* d, const uint32_t* a,
                                         uint32_t b0, uint32_t b1) {
    asm volatile(
        "mma.sync.aligned.m16n8k16.row.col.f32.bf16.bf16.f32 "
        "{%0,%1,%2,%3}, {%4,%5,%6,%7}, {%8,%9}, {%0,%1,%2,%3};"
        : "+f"(d[0]), "+f"(d[1]), "+f"(d[2]), "+f"(d[3])
        : "r"(a[0]), "r"(a[1]), "r"(a[2]), "r"(a[3]), "r"(b0), "r"(b1));
}

// ---------------------------------------------------------------------------
// Preprocess: per-row norm + bf16 hi/lo split for both matrices.
// ---------------------------------------------------------------------------
__global__ __launch_bounds__(128) void prep_kernel(
    const float* __restrict__ target, const float* __restrict__ ss)
{
    int row = blockIdx.x;
    bool is_t = row < NROWS;
    int r = is_t ? row : row - NROWS;
    const float* src = (is_t ? target : ss) + (size_t)r * DIM;
    __nv_bfloat16* hi = (is_t ? g_Ahi : g_Bhi) + (size_t)r * DIM;
    __nv_bfloat16* lo = (is_t ? g_Alo : g_Blo) + (size_t)r * DIM;

    float s = 0.f;
    #pragma unroll
    for (int j = 0; j < DIM / 128; j++) {
        int i = threadIdx.x + j * 128;
        float x = src[i];
        s += x * x;
        __nv_bfloat16 h = __float2bfloat16(x);
        __nv_bfloat16 l = __float2bfloat16(x - __bfloat162float(h));
        hi[i] = h;
        lo[i] = l;
    }
    #pragma unroll
    for (int off = 16; off > 0; off >>= 1)
        s += __shfl_down_sync(0xFFFFFFFFu, s, off);
    __shared__ float ws[4];
    if ((threadIdx.x & 31) == 0) ws[threadIdx.x >> 5] = s;
    __syncthreads();
    if (threadIdx.x == 0) {
        float n = sqrtf(ws[0] + ws[1] + ws[2] + ws[3]);
        if (is_t) g_tn[r] = n; else g_sn[r] = n;
    }
}

// ---------------------------------------------------------------------------
// bf16-split mma.sync GEMM + cosine epilogue.
// 128x128 CTA tile, 8 warps (2 M x 4 N), warp tile 64x32, m16n8k16 frags.
// 3-stage cp.async pipeline, ONE __syncthreads per tile.
// ---------------------------------------------------------------------------
__global__ __launch_bounds__(256, 2) void cosine_mma_kernel(float* __restrict__ C)
{
    extern __shared__ char smem[];
    const uint32_t smem_base = smem_u32(smem);
    const int tid  = threadIdx.x;
    const int wid  = tid >> 5;
    const int lane = tid & 31;
    const int bm = blockIdx.y * BM;
    const int bn = blockIdx.x * BN;

    const int warp_m = (wid >> 2) * 64;  // 0 or 64
    const int warp_n = (wid & 3) * 32;   // 0,32,64,96

    // ---- loader address precompute ----
    const int ldr = tid >> 3;            // 0..31
    const int ldc = tid & 7;             // 0..7
    const uint32_t dst0 = swz((uint32_t)(ldr * 128 + ldc * 16));  // +i*4096 per pass
    const size_t srcA_off = (size_t)(bm + ldr) * DIM + ldc * 8;
    const size_t srcB_off = (size_t)(bn + ldr) * DIM + ldc * 8;

    // ---- ldmatrix address precompute ----
    const int lrow = ((lane >> 3) & 1) * 8 + (lane & 7);
    const int cx   = (lane >> 4) * 16;
    const uint32_t xorv = (uint32_t)((lrow & 7) * 16);
    uint32_t aoff[4], boff[2], colx[4];
    #pragma unroll
    for (int mf = 0; mf < 4; mf++)
        aoff[mf] = (uint32_t)((warp_m + mf * 16 + lrow) * 128);
    #pragma unroll
    for (int np = 0; np < 2; np++)
        boff[np] = (uint32_t)((warp_n + np * 16 + lrow) * 128);
    #pragma unroll
    for (int ks = 0; ks < 4; ks++)
        colx[ks] = (uint32_t)(ks * 32 + cx) ^ xorv;

    float acc[4][4][4];
    #pragma unroll
    for (int i = 0; i < 4; i++)
        #pragma unroll
        for (int j = 0; j < 4; j++)
            #pragma unroll
            for (int v = 0; v < 4; v++) acc[i][j][v] = 0.f;

    // ---- issue one tile's loads into a stage slot ----
    auto issue_load = [&](int tile, int slot) {
        const int part = tile >> 4;
        const int kk = (tile & 15) * BK;
        const __nv_bfloat16* pA = ((part == 2) ? g_Alo : g_Ahi) + srcA_off + kk;
        const __nv_bfloat16* pB = ((part == 1) ? g_Blo : g_Bhi) + srcB_off + kk;
        const uint32_t da = smem_base + slot * SMEM_STAGE + dst0;
        const uint32_t db = da + SMEM_BOFF;
        #pragma unroll
        for (int i = 0; i < 4; i++) {
            cp16(da + i * 4096, pA + (size_t)i * 32 * DIM);
            cp16(db + i * 4096, pB + (size_t)i * 32 * DIM);
        }
        CP_COMMIT();
    };

    // ---- prologue: tiles 0 and 1 in flight ----
    issue_load(0, 0);
    issue_load(1, 1);

    int slot = 0;
    for (int t = 0; t < NTILES; t++) {
        if (t < NTILES - 1) CP_WAIT(1); else CP_WAIT(0);
        __syncthreads();

        const uint32_t ab = smem_base + slot * SMEM_STAGE;
        const uint32_t bb = ab + SMEM_BOFF;

        // preload ks=0 fragments first (start shared pipe before cp issue)
        uint32_t afr[2][4][4], bfr[2][2][4];
        #pragma unroll
        for (int mf = 0; mf < 4; mf++) ldsm4(afr[0][mf], ab + aoff[mf] + colx[0]);
        #pragma unroll
        for (int np = 0; np < 2; np++) ldsm4(bfr[0][np], bb + boff[np] + colx[0]);

        // issue loads for tile t+2 into the slot tile t-1 used
        if (t + 2 < NTILES) {
            int wslot = slot + 2; if (wslot >= NSTAGES) wslot -= NSTAGES;
            issue_load(t + 2, wslot);
        }

        #pragma unroll
        for (int ks = 0; ks < 4; ks++) {
            const int cur = ks & 1;
            if (ks < 3) {
                const int nxt = cur ^ 1;
                #pragma unroll
                for (int mf = 0; mf < 4; mf++)
                    ldsm4(afr[nxt][mf], ab + aoff[mf] + colx[ks + 1]);
                #pragma unroll
                for (int np = 0; np < 2; np++)
                    ldsm4(bfr[nxt][np], bb + boff[np] + colx[ks + 1]);
            }
            #pragma unroll
            for (int mf = 0; mf < 4; mf++) {
                #pragma unroll
                for (int nf = 0; nf < 4; nf++) {
                    const int np = nf >> 1, hi = nf & 1;
                    mma16816(acc[mf][nf], afr[cur][mf],
                             bfr[cur][np][hi], bfr[cur][np][2 + hi]);
                }
            }
        }
        if (++slot == NSTAGES) slot = 0;
    }

    // ---- epilogue: cosine normalize + store ----
    #pragma unroll
    for (int mf = 0; mf < 4; mf++) {
        const int row0 = bm + warp_m + mf * 16 + (lane >> 2);
        const int row1 = row0 + 8;
        const float tn0 = g_tn[row0];
        const float tn1 = g_tn[row1];
        float* Cr0 = C + (size_t)row0 * NROWS;
        float* Cr1 = C + (size_t)row1 * NROWS;
        #pragma unroll
        for (int nf = 0; nf < 4; nf++) {
            const int col = bn + warp_n + nf * 8 + (lane & 3) * 2;
            const float sn0 = g_sn[col];
            const float sn1 = g_sn[col + 1];
            float2 v0, v1;
            v0.x = acc[mf][nf][0] / fmaxf(tn0 * sn0, EPS);
            v0.y = acc[mf][nf][1] / fmaxf(tn0 * sn1, EPS);
            v1.x = acc[mf][nf][2] / fmaxf(tn1 * sn0, EPS);
            v1.y = acc[mf][nf][3] / fmaxf(tn1 * sn1, EPS);
            *(float2*)(Cr0 + col) = v0;
            *(float2*)(Cr1 + col) = v1;
        }
    }
}

// ---------------------------------------------------------------------------
extern "C" void kernel_launch(void* const* d_in, const int* in_sizes, int n_in,
                              void* d_out, int out_size)
{
    const float* target = (const float*)d_in[0];
    const float* ss     = (const float*)d_in[1];
    float* out          = (float*)d_out;

    cudaFuncSetAttribute(cosine_mma_kernel,
                         cudaFuncAttributeMaxDynamicSharedMemorySize, SMEM_TOTAL);

    prep_kernel<<<2 * NROWS, 128>>>(target, ss);

    dim3 grid(NROWS / BN, NROWS / BM);   // 32 x 32
    cosine_mma_kernel<<<grid, 256, SMEM_TOTAL>>>(out);
}

// round 10
// speedup vs baseline: 1.0533x; 1.0533x over previous
#include <cuda_runtime.h>
#include <cuda_bf16.h>
#include <math.h>
#include <stdint.h>

#define NROWS 4096
#define DIM   1024
#define EPS   1e-8f

// GEMM tiling
#define BM 128
#define BN 128
#define BK 64                      // bf16 K per smem tile (128 B rows, SW128 image)
#define NTILES_K (DIM / BK)        // 16
#define NPARTS 3                   // hi*hi, hi*lo, lo*hi
#define NTILES (NPARTS * NTILES_K) // 48

#define TILE_BYTES 16384           // 128 rows x 128 B
// dynamic smem: double-buffered (A 16KB + B 16KB)
#define SMEM_A0 0
#define SMEM_A1 32768
#define SMEM_BOFF 16384
#define SMEM_TOTAL 65536

// Scratch: tiled+swizzled bf16 images.
// Layout (bytes): ((rowblock*16 + ktile) * 16384) + swz(r*128 + c16*16)
__device__ __nv_bfloat16 g_Ahi[NROWS * DIM];
__device__ __nv_bfloat16 g_Alo[NROWS * DIM];
__device__ __nv_bfloat16 g_Bhi[NROWS * DIM];
__device__ __nv_bfloat16 g_Blo[NROWS * DIM];
__device__ float g_tn[NROWS];
__device__ float g_sn[NROWS];

// ---------------------------------------------------------------------------
// helpers
// ---------------------------------------------------------------------------
__device__ __forceinline__ uint32_t smem_u32(const void* p) {
    uint32_t a;
    asm("{ .reg .u64 t; cvta.to.shared.u64 t, %1; cvt.u32.u64 %0, t; }"
        : "=r"(a) : "l"(p));
    return a;
}
__device__ __forceinline__ void cp16(uint32_t dst, const void* src) {
    asm volatile("cp.async.cg.shared.global [%0], [%1], 16;"
                 :: "r"(dst), "l"(src));
}
#define CP_COMMIT() asm volatile("cp.async.commit_group;" ::: "memory")
#define CP_WAIT(n)  asm volatile("cp.async.wait_group %0;" :: "n"(n) : "memory")

__device__ __forceinline__ uint32_t swz(uint32_t o) {   // SW128: bits[6:4] ^= bits[9:7]
    return o ^ ((o >> 3) & 0x70);
}
__device__ __forceinline__ void ldsm4(uint32_t* r, uint32_t a) {
    asm volatile("ldmatrix.sync.aligned.m8n8.x4.shared.b16 {%0,%1,%2,%3}, [%4];"
                 : "=r"(r[0]), "=r"(r[1]), "=r"(r[2]), "=r"(r[3]) : "r"(a));
}
__device__ __forceinline__ void mma16816(float* d, const uint32_t* a,
                                         uint32_t b0, uint32_t b1) {
    asm volatile(
        "mma.sync.aligned.m16n8k16.row.col.f32.bf16.bf16.f32 "
        "{%0,%1,%2,%3}, {%4,%5,%6,%7}, {%8,%9}, {%0,%1,%2,%3};"
        : "+f"(d[0]), "+f"(d[1]), "+f"(d[2]), "+f"(d[3])
        : "r"(a[0]), "r"(a[1]), "r"(a[2]), "r"(a[3]), "r"(b0), "r"(b1));
}

// ---------------------------------------------------------------------------
// Preprocess: per-row norm + bf16 hi/lo split, stored PRE-SWIZZLED per tile.
// One block per row (8192 blocks); thread tid owns 16B chunk tid (8 elems).
// ---------------------------------------------------------------------------
__global__ __launch_bounds__(128) void prep_kernel(
    const float* __restrict__ target, const float* __restrict__ ss)
{
    int row = blockIdx.x;
    bool is_t = row < NROWS;
    int r = is_t ? row : row - NROWS;
    const float4* src = (const float4*)((is_t ? target : ss) + (size_t)r * DIM);
    char* hi_c = (char*)(is_t ? g_Ahi : g_Bhi);
    char* lo_c = (char*)(is_t ? g_Alo : g_Blo);

    const int tid = threadIdx.x;           // chunk index 0..127
    float4 v0 = src[tid * 2];
    float4 v1 = src[tid * 2 + 1];

    float s = v0.x * v0.x + v0.y * v0.y + v0.z * v0.z + v0.w * v0.w
            + v1.x * v1.x + v1.y * v1.y + v1.z * v1.z + v1.w * v1.w;

    // split into hi/lo bf16x2 words
    float x[8] = {v0.x, v0.y, v0.z, v0.w, v1.x, v1.y, v1.z, v1.w};
    uint32_t hw[4], lw[4];
    #pragma unroll
    for (int q = 0; q < 4; q++) {
        float x0 = x[q * 2], x1 = x[q * 2 + 1];
        __nv_bfloat162 h2 = __floats2bfloat162_rn(x0, x1);
        float h0 = __bfloat162float(__low2bfloat16(h2));
        float h1 = __bfloat162float(__high2bfloat16(h2));
        __nv_bfloat162 l2 = __floats2bfloat162_rn(x0 - h0, x1 - h1);
        hw[q] = *(uint32_t*)&h2;
        lw[q] = *(uint32_t*)&l2;
    }

    const int kt = tid >> 3;               // ktile 0..15
    const int j  = tid & 7;                // 16B col within tile
    size_t base = ((size_t)(r >> 7) * 16 + kt) * TILE_BYTES
                + swz((uint32_t)((r & 127) * 128 + j * 16));
    *(uint4*)(hi_c + base) = make_uint4(hw[0], hw[1], hw[2], hw[3]);
    *(uint4*)(lo_c + base) = make_uint4(lw[0], lw[1], lw[2], lw[3]);

    // norm reduce
    #pragma unroll
    for (int off = 16; off > 0; off >>= 1)
        s += __shfl_down_sync(0xFFFFFFFFu, s, off);
    __shared__ float ws[4];
    if ((tid & 31) == 0) ws[tid >> 5] = s;
    __syncthreads();
    if (tid == 0) {
        float n = sqrtf(ws[0] + ws[1] + ws[2] + ws[3]);
        if (is_t) g_tn[r] = n; else g_sn[r] = n;
    }
}

// ---------------------------------------------------------------------------
// bf16-split mma.sync GEMM + cosine epilogue.
// 128x128 CTA tile, 8 warps (2 M x 4 N), warp tile 64x32, m16n8k16 frags.
// 2-stage cp.async pipeline; loads are LINEAR copies of pre-swizzled tiles.
// ---------------------------------------------------------------------------
__global__ __launch_bounds__(256, 2) void cosine_mma_kernel(float* __restrict__ C)
{
    extern __shared__ char smem[];
    const uint32_t smem_base = smem_u32(smem);
    const int tid  = threadIdx.x;
    const int wid  = tid >> 5;
    const int lane = tid & 31;
    const int bm = blockIdx.y * BM;
    const int bn = blockIdx.x * BN;

    const int warp_m = (wid >> 2) * 64;  // 0 or 64
    const int warp_n = (wid & 3) * 32;   // 0,32,64,96

    // ---- loader: linear chunk tid*16, 4 passes of 4KB each per matrix ----
    const uint32_t dstA = smem_base + tid * 16;          // + buf*32768 (+16384 for B)
    const size_t   srcc = (size_t)tid * 16;              // chunk byte offset in tile
    const size_t   abase = (size_t)(bm >> 7) * 16 * TILE_BYTES;
    const size_t   bbase = (size_t)(bn >> 7) * 16 * TILE_BYTES;

    // ---- ldmatrix address precompute ----
    const int lrow = ((lane >> 3) & 1) * 8 + (lane & 7);
    const int cx   = (lane >> 4) * 16;
    const uint32_t xorv = (uint32_t)((lrow & 7) * 16);
    uint32_t aoff[4], boff[2], colx[4];
    #pragma unroll
    for (int mf = 0; mf < 4; mf++)
        aoff[mf] = (uint32_t)((warp_m + mf * 16 + lrow) * 128);
    #pragma unroll
    for (int np = 0; np < 2; np++)
        boff[np] = (uint32_t)((warp_n + np * 16 + lrow) * 128);
    #pragma unroll
    for (int ks = 0; ks < 4; ks++)
        colx[ks] = (uint32_t)(ks * 32 + cx) ^ xorv;

    float acc[4][4][4];
    #pragma unroll
    for (int i = 0; i < 4; i++)
        #pragma unroll
        for (int j = 0; j < 4; j++)
            #pragma unroll
            for (int v = 0; v < 4; v++) acc[i][j][v] = 0.f;

    auto issue_load = [&](int tile, int buf) {
        const int part = tile >> 4;
        const size_t kb = (size_t)(tile & 15) * TILE_BYTES;
        const char* pA = (const char*)((part == 2) ? g_Alo : g_Ahi) + abase + kb + srcc;
        const char* pB = (const char*)((part == 1) ? g_Blo : g_Bhi) + bbase + kb + srcc;
        const uint32_t da = dstA + buf * 32768;
        #pragma unroll
        for (int i = 0; i < 4; i++) {
            cp16(da + i * 4096, pA + i * 4096);
            cp16(da + SMEM_BOFF + i * 4096, pB + i * 4096);
        }
        CP_COMMIT();
    };

    // ---- prologue ----
    issue_load(0, 0);

    for (int t = 0; t < NTILES; t++) {
        const int buf = t & 1;
        if (t + 1 < NTILES) {
            issue_load(t + 1, buf ^ 1);
            CP_WAIT(1);
        } else {
            CP_WAIT(0);
        }
        __syncthreads();

        const uint32_t ab = smem_base + buf * 32768;
        const uint32_t bb = ab + SMEM_BOFF;

        uint32_t afr[2][4][4], bfr[2][2][4];
        #pragma unroll
        for (int mf = 0; mf < 4; mf++) ldsm4(afr[0][mf], ab + aoff[mf] + colx[0]);
        #pragma unroll
        for (int np = 0; np < 2; np++) ldsm4(bfr[0][np], bb + boff[np] + colx[0]);

        #pragma unroll
        for (int ks = 0; ks < 4; ks++) {
            const int cur = ks & 1;
            if (ks < 3) {
                const int nxt = cur ^ 1;
                #pragma unroll
                for (int mf = 0; mf < 4; mf++)
                    ldsm4(afr[nxt][mf], ab + aoff[mf] + colx[ks + 1]);
                #pragma unroll
                for (int np = 0; np < 2; np++)
                    ldsm4(bfr[nxt][np], bb + boff[np] + colx[ks + 1]);
            }
            #pragma unroll
            for (int mf = 0; mf < 4; mf++) {
                #pragma unroll
                for (int nf = 0; nf < 4; nf++) {
                    const int np = nf >> 1, hi = nf & 1;
                    mma16816(acc[mf][nf], afr[cur][mf],
                             bfr[cur][np][hi], bfr[cur][np][2 + hi]);
                }
            }
        }
        __syncthreads();
    }

    // ---- epilogue: cosine normalize + store ----
    #pragma unroll
    for (int mf = 0; mf < 4; mf++) {
        const int row0 = bm + warp_m + mf * 16 + (lane >> 2);
        const int row1 = row0 + 8;
        const float tn0 = g_tn[row0];
        const float tn1 = g_tn[row1];
        float* Cr0 = C + (size_t)row0 * NROWS;
        float* Cr1 = C + (size_t)row1 * NROWS;
        #pragma unroll
        for (int nf = 0; nf < 4; nf++) {
            const int col = bn + warp_n + nf * 8 + (lane & 3) * 2;
            const float sn0 = g_sn[col];
            const float sn1 = g_sn[col + 1];
            float2 v0, v1;
            v0.x = acc[mf][nf][0] / fmaxf(tn0 * sn0, EPS);
            v0.y = acc[mf][nf][1] / fmaxf(tn0 * sn1, EPS);
            v1.x = acc[mf][nf][2] / fmaxf(tn1 * sn0, EPS);
            v1.y = acc[mf][nf][3] / fmaxf(tn1 * sn1, EPS);
            *(float2*)(Cr0 + col) = v0;
            *(float2*)(Cr1 + col) = v1;
        }
    }
}

// ---------------------------------------------------------------------------
extern "C" void kernel_launch(void* const* d_in, const int* in_sizes, int n_in,
                              void* d_out, int out_size)
{
    const float* target = (const float*)d_in[0];
    const float* ss     = (const float*)d_in[1];
    float* out          = (float*)d_out;

    cudaFuncSetAttribute(cosine_mma_kernel,
                         cudaFuncAttributeMaxDynamicSharedMemorySize, SMEM_TOTAL);

    prep_kernel<<<2 * NROWS, 128>>>(target, ss);

    dim3 grid(NROWS / BN, NROWS / BM);   // 32 x 32
    cosine_mma_kernel<<<grid, 256, SMEM_TOTAL>>>(out);
}